// round 13
// baseline (speedup 1.0000x reference)
#include <cuda_runtime.h>

typedef unsigned long long u64;
typedef unsigned int u32;

#define DD 1024
#define BB 64
#define BETA_W 0.001f

// Junction cascade over a gapped, position-indexed block array with edge pointers.
__device__ void cascade(float2* b, int* jl, int* jr, int ls, int junc, int re) {
    int li = junc - 1;
    float2 L = b[li];
    if (L.y == 0.0f) { li = jl[li]; L = b[li]; }
    float2 P = b[junc];
    if (!(L.x * P.y < P.x * L.y)) return;
    P.x += L.x; P.y += L.y;
    b[li].y = 0.0f;
    b[junc].y = 0.0f;
    int lpos = li;
    int lc = li - 1;
    int rc = junc + 1;
    int lstop = ls - 1;
    int rstop = re;
    bool changed = true;
    while (changed) {
        changed = false;
        while (lc >= ls) {
            float2 Lb = b[lc];
            if (Lb.y == 0.0f) { lc = jl[lc]; if (lc < ls) break; Lb = b[lc]; }
            if (Lb.x * P.y < P.x * Lb.y) {
                P.x += Lb.x; P.y += Lb.y;
                b[lc].y = 0.0f;
                lpos = lc; --lc; changed = true;
            } else { lstop = lc; break; }
        }
        while (rc < re) {
            float2 Rb = b[rc];
            if (Rb.y == 0.0f) { rc = jr[rc]; if (rc >= re) break; Rb = b[rc]; }
            if (Rb.x * P.y > P.x * Rb.y) {
                P.x += Rb.x; P.y += Rb.y;
                b[rc].y = 0.0f;
                ++rc; changed = true;
            } else { rstop = rc; break; }
        }
    }
    b[lpos] = P;
    if (lpos - 1 > lstop) { jl[lpos - 1] = lstop; jr[lstop + 1] = lpos; }
    if (rstop - 1 > lpos) { jl[rstop - 1] = lpos; jr[lpos + 1] = rstop; }
}

__global__ __launch_bounds__(1024) void oscarmax_kernel(const float* __restrict__ x,
                                                        float* __restrict__ out) {
    __shared__ u64   sbuf[2][DD];      // scatter buf / sorted buf; after: bA | jl/jr
    __shared__ int   cnt[DD];          // bucket sizes
    __shared__ int   basx[DD];         // bucket start (exclusive scan)
    __shared__ int   offs[DD];         // running scatter offsets
    __shared__ int   part_b[32];       // fill max-scan
    __shared__ int   part_c[32];       // bucket scan + rank scan (barrier-separated)
    __shared__ float part_p[32];       // positive-sum scan
    __shared__ float part_n[32];       // negative-sum scan
    __shared__ float tau_sh;

    float2* bA = (float2*)&sbuf[0][0];
    int*    jl = (int*)&sbuf[1][0];
    int*    jr = jl + DD;
    u64*    s64a = &sbuf[0][0];        // scattered (unordered within bucket)
    u64*    s64b = &sbuf[1][0];        // fully sorted

    const int tid  = threadIdx.x;
    const int lane = tid & 31;
    const int wrp  = tid >> 5;
    const int row  = blockIdx.x;
    const unsigned FULL = 0xffffffffu;

    // ---- load, pack sortable u64: key=|x| bits (desc), payload=(idx<<1)|negbit ----
    float xv = x[row * DD + tid];
    float ax = fabsf(xv);
    u32 kb = __float_as_uint(ax);
    u32 pl = ((u32)tid << 1) | (xv < 0.0f ? 1u : 0u);
    u64 v = ((u64)kb << 32) | pl;

    // ---- bucket sort (descending): monotone bucket, exact in-bucket ranking ----
    int bkt = 1023 - min(1023, (int)(ax * 256.0f));   // descending bucket order
    cnt[tid] = 0;
    __syncthreads();
    atomicAdd(&cnt[bkt], 1);
    __syncthreads();

    // exclusive scan of cnt -> basx (and offs copy for scatter atomics)
    {
        int csz = cnt[tid];
        int inc = csz;
        #pragma unroll
        for (int o = 1; o < 32; o <<= 1) {
            int t = __shfl_up_sync(FULL, inc, o);
            if (lane >= o) inc += t;
        }
        if (lane == 31) part_c[wrp] = inc;
        __syncthreads();
        if (tid < 32) {
            int p = part_c[tid];
            #pragma unroll
            for (int o = 1; o < 32; o <<= 1) {
                int t = __shfl_up_sync(FULL, p, o);
                if (tid >= o) p += t;
            }
            part_c[tid] = p;
        }
        __syncthreads();
        if (wrp > 0) inc += part_c[wrp - 1];
        int excl = inc - csz;
        basx[tid] = excl;
        offs[tid] = excl;
    }
    __syncthreads();

    // scatter into bucket region (unordered within bucket)
    {
        int slot = atomicAdd(&offs[bkt], 1);
        s64a[slot] = v;
    }
    __syncthreads();

    // exact within-bucket rank (descending): r = #{peer > v}; place at basx+r
    {
        int st = basx[bkt];
        int sz = cnt[bkt];
        int r = 0;
        #pragma unroll 1
        for (int q = 0; q < sz; q++) {
            u64 u = s64a[st + q];
            r += (u > v) ? 1 : 0;
        }
        s64b[st + r] = v;
    }
    __syncthreads();
    v = s64b[tid];      // fully sorted descending, strict total order -> deterministic

    // ---- unpack: key, index, sign all from the sorted word ----
    float keyf  = __uint_as_float((u32)(v >> 32));
    u32   plo   = (u32)v;
    int   idx   = (int)(plo >> 1);
    float sgn_i = (plo & 1u) ? -1.0f : 1.0f;
    float sval  = keyf - BETA_W * (float)(DD - 1 - tid);
    __syncthreads();     // all sorted reads done; sbuf dead -> bA / jl / jr

    // ---- per-chunk PAVA: 16-elem chunks, two per warp via width-16 shfl segments ----
    {
        const int sub   = lane >> 4;                    // 0 or 1: which half-warp
        const int slane = lane & 15;
        const unsigned smask = 0xFFFFu << (sub << 4);   // this half's lanes only
        const int base = tid & ~15;                     // chunk base position

        bA[tid] = make_float2(0.0f, 0.0f);              // clear own slot
        __syncwarp();

        float psum = 0.0f, pcnt = 0.0f;                 // stack entry owned by this lane
        int   ppos = 0;
        int nb = 0;
        float ts = __shfl_sync(smask, sval, 0, 16), tc = 1.0f;
        int tpos = 0;
        #pragma unroll 1
        for (int i = 1; i < 16; i++) {
            float cs = __shfl_sync(smask, sval, i, 16), cc = 1.0f;
            int cpos = i;
            for (;;) {
                if (cs * tc > ts * cc) {                // cur_mean > top_mean: pool
                    cs += ts; cc += tc; cpos = tpos;
                    if (nb > 0) {
                        --nb;
                        ts   = __shfl_sync(smask, psum, nb, 16);
                        tc   = __shfl_sync(smask, pcnt, nb, 16);
                        tpos = __shfl_sync(smask, ppos, nb, 16);
                    } else { ts = cs; tc = cc; tpos = cpos; goto nexti; }
                } else break;
            }
            if (slane == nb) { psum = ts; pcnt = tc; ppos = tpos; }
            nb++;
            ts = cs; tc = cc; tpos = cpos;
            nexti: ;
        }
        if (slane == nb) { psum = ts; pcnt = tc; ppos = tpos; }
        nb++;
        __syncwarp();                                   // halves reconverged; order clears

        if (slane < nb) {
            int st = base + ppos;
            int c  = (int)pcnt;
            bA[st] = make_float2(psum, pcnt);
            if (c > 1) {
                jr[st + 1]     = st + c;
                jl[st + c - 1] = st;
            }
        }
    }
    __syncthreads();     // bA, jl/jr visible

    // ---- merge tree: 6 levels (64 chunks), one cascade per WARP ----
    #pragma unroll 1
    for (int L = 0; L < 6; L++) {
        int npairs = 32 >> L;
        if (lane == 0 && wrp < npairs) {
            int seg = 32 << L;
            int ls  = wrp * seg;
            cascade(bA, jl, jr, ls, ls + (seg >> 1), ls + seg);
        }
        __syncthreads();
    }

    // ---- fill-forward: valid slot index max-scan gives each position its block start ----
    float2 bme = bA[tid];
    int mp = (bme.y > 0.0f) ? tid : -1;
    #pragma unroll
    for (int o = 1; o < 32; o <<= 1) {
        int t = __shfl_up_sync(FULL, mp, o);
        if (lane >= o) mp = max(mp, t);
    }
    if (lane == 31) part_b[wrp] = mp;
    __syncthreads();
    if (tid < 32) {
        int p = part_b[tid];
        #pragma unroll
        for (int o = 1; o < 32; o <<= 1) {
            int t = __shfl_up_sync(FULL, p, o);
            if (tid >= o) p = max(p, t);
        }
        part_b[tid] = p;
    }
    __syncthreads();
    if (wrp > 0) mp = max(mp, part_b[wrp - 1]);

    float2 blk = bA[mp];                       // block containing position tid
    float y = fmaxf(blk.x / blk.y, 0.0f);      // pooled mean, clamped; nonincreasing in tid
    float z = sgn_i * y;                       // oscar prox at sorted position tid

    // ---- fused epilogue: one combined scan -> rank AND sorted cumsum ----
    {
        int fP = (z > 0.0f) ? 1 : 0;
        int fN = (z < 0.0f) ? 1 : 0;
        int   pk = (fP << 16) | fN;
        float zp = fP ? z : 0.0f;
        float zn = fN ? z : 0.0f;
        int   ipk = pk;
        float izp = zp, izn = zn;
        #pragma unroll
        for (int o = 1; o < 32; o <<= 1) {
            int   ti = __shfl_up_sync(FULL, ipk, o);
            float tp = __shfl_up_sync(FULL, izp, o);
            float tn = __shfl_up_sync(FULL, izn, o);
            if (lane >= o) { ipk += ti; izp += tp; izn += tn; }
        }
        if (lane == 31) { part_c[wrp] = ipk; part_p[wrp] = izp; part_n[wrp] = izn; }
        __syncthreads();
        if (tid < 32) {
            int   p  = part_c[tid];
            float pp = part_p[tid];
            float pn = part_n[tid];
            #pragma unroll
            for (int o = 1; o < 32; o <<= 1) {
                int   ti = __shfl_up_sync(FULL, p,  o);
                float tp = __shfl_up_sync(FULL, pp, o);
                float tn = __shfl_up_sync(FULL, pn, o);
                if (tid >= o) { p += ti; pp += tp; pn += tn; }
            }
            part_c[tid] = p; part_p[tid] = pp; part_n[tid] = pn;
        }
        __syncthreads();
        if (wrp > 0) {
            ipk += part_c[wrp - 1];
            izp += part_p[wrp - 1];
            izn += part_n[wrp - 1];
        }
        int   total = part_c[31];
        float totP  = part_p[31];
        float totN  = part_n[31];

        int excl = ipk - pk;
        int pPex = excl >> 16;
        int pNex = excl & 0xffff;
        int totalPcnt = total >> 16;

        int pos;
        float c;
        if (z > 0.0f)      { pos = pPex;                            c = izp; }
        else if (z < 0.0f) { pos = DD - 1 - pNex;                   c = (totP + totN) - (izn - zn); }
        else               { pos = totalPcnt + (tid - pPex - pNex); c = totP; }

        bool flag = (1.0f + (float)(pos + 1) * z) > c;
        int k_sup = __syncthreads_count(flag);        // support is a prefix in sorted order
        if (pos == k_sup - 1) tau_sh = (c - 1.0f) / (float)k_sup;
        __syncthreads();

        out[row * DD + idx] = fmaxf(z - tau_sh, 0.0f);
    }
}

extern "C" void kernel_launch(void* const* d_in, const int* in_sizes, int n_in,
                              void* d_out, int out_size) {
    const float* x = (const float*)d_in[0];
    float* out = (float*)d_out;
    oscarmax_kernel<<<BB, DD>>>(x, out);
}

// round 14
// speedup vs baseline: 1.0118x; 1.0118x over previous
#include <cuda_runtime.h>

typedef unsigned long long u64;
typedef unsigned int u32;

#define DD 1024
#define BB 64
#define BETA_W 0.001f

// Junction cascade over a gapped, position-indexed block array with edge pointers.
__device__ void cascade(float2* b, int* jl, int* jr, int ls, int junc, int re) {
    int li = junc - 1;
    float2 L = b[li];
    if (L.y == 0.0f) { li = jl[li]; L = b[li]; }
    float2 P = b[junc];
    if (!(L.x * P.y < P.x * L.y)) return;
    P.x += L.x; P.y += L.y;
    b[li].y = 0.0f;
    b[junc].y = 0.0f;
    int lpos = li;
    int lc = li - 1;
    int rc = junc + 1;
    int lstop = ls - 1;
    int rstop = re;
    bool changed = true;
    while (changed) {
        changed = false;
        while (lc >= ls) {
            float2 Lb = b[lc];
            if (Lb.y == 0.0f) { lc = jl[lc]; if (lc < ls) break; Lb = b[lc]; }
            if (Lb.x * P.y < P.x * Lb.y) {
                P.x += Lb.x; P.y += Lb.y;
                b[lc].y = 0.0f;
                lpos = lc; --lc; changed = true;
            } else { lstop = lc; break; }
        }
        while (rc < re) {
            float2 Rb = b[rc];
            if (Rb.y == 0.0f) { rc = jr[rc]; if (rc >= re) break; Rb = b[rc]; }
            if (Rb.x * P.y > P.x * Rb.y) {
                P.x += Rb.x; P.y += Rb.y;
                b[rc].y = 0.0f;
                ++rc; changed = true;
            } else { rstop = rc; break; }
        }
    }
    b[lpos] = P;
    if (lpos - 1 > lstop) { jl[lpos - 1] = lstop; jr[lstop + 1] = lpos; }
    if (rstop - 1 > lpos) { jl[rstop - 1] = lpos; jr[lpos + 1] = rstop; }
}

__global__ __launch_bounds__(1024) void oscarmax_kernel(const float* __restrict__ x,
                                                        float* __restrict__ out) {
    __shared__ u64   sbuf[2][DD];      // scatter buf / sorted buf; after: bA | jl/jr
    __shared__ int   cnt[DD];          // bucket sizes
    __shared__ int   offs[DD];         // scatter offsets (post-scatter: start+size)
    __shared__ int   part_b[32];       // fill max-scan
    __shared__ int   part_c[32];       // bucket scan + rank scan (barrier-separated)
    __shared__ float part_p[32];       // positive-sum scan
    __shared__ float part_n[32];       // negative-sum scan
    __shared__ float tau_sh;

    float2* bA = (float2*)&sbuf[0][0];
    int*    jl = (int*)&sbuf[1][0];
    int*    jr = jl + DD;
    u64*    s64a = &sbuf[0][0];        // scattered (unordered within bucket)
    u64*    s64b = &sbuf[1][0];        // fully sorted

    const int tid  = threadIdx.x;
    const int lane = tid & 31;
    const int wrp  = tid >> 5;
    const int row  = blockIdx.x;
    const unsigned FULL = 0xffffffffu;

    // ---- load, pack sortable u64: key=|x| bits (desc), payload=(idx<<1)|negbit ----
    float xv = x[row * DD + tid];
    float ax = fabsf(xv);
    u32 kb = __float_as_uint(ax);
    u32 pl = ((u32)tid << 1) | (xv < 0.0f ? 1u : 0u);
    u64 v = ((u64)kb << 32) | pl;

    // ---- bucket sort (descending): monotone bucket, exact in-bucket ranking ----
    int bkt = 1023 - min(1023, (int)(ax * 256.0f));   // descending bucket order
    cnt[tid] = 0;
    __syncthreads();
    atomicAdd(&cnt[bkt], 1);
    __syncthreads();

    // exclusive scan of cnt -> offs (scatter cursor)
    {
        int csz = cnt[tid];
        int inc = csz;
        #pragma unroll
        for (int o = 1; o < 32; o <<= 1) {
            int t = __shfl_up_sync(FULL, inc, o);
            if (lane >= o) inc += t;
        }
        if (lane == 31) part_c[wrp] = inc;
        __syncthreads();
        if (tid < 32) {
            int p = part_c[tid];
            #pragma unroll
            for (int o = 1; o < 32; o <<= 1) {
                int t = __shfl_up_sync(FULL, p, o);
                if (tid >= o) p += t;
            }
            part_c[tid] = p;
        }
        __syncthreads();
        if (wrp > 0) inc += part_c[wrp - 1];
        offs[tid] = inc - csz;
    }
    __syncthreads();

    // scatter into bucket region (unordered within bucket)
    {
        int slot = atomicAdd(&offs[bkt], 1);
        s64a[slot] = v;
    }
    __syncthreads();

    // exact within-bucket rank (descending): r = #{peer > v}; place at start+r
    // post-scatter offs[bkt] == start + size
    {
        int sz = cnt[bkt];
        int st = offs[bkt] - sz;
        int r = 0;
        #pragma unroll 1
        for (int q = 0; q < sz; q++) {
            u64 u = s64a[st + q];
            r += (u > v) ? 1 : 0;
        }
        s64b[st + r] = v;
    }
    __syncthreads();
    v = s64b[tid];      // fully sorted descending, strict total order -> deterministic

    // ---- unpack: key, index, sign all from the sorted word ----
    float keyf  = __uint_as_float((u32)(v >> 32));
    u32   plo   = (u32)v;
    int   idx   = (int)(plo >> 1);
    float sgn_i = (plo & 1u) ? -1.0f : 1.0f;
    float sval  = keyf - BETA_W * (float)(DD - 1 - tid);
    __syncthreads();     // all sorted reads done; sbuf dead -> bA / jl / jr

    // ---- per-chunk PAVA: register stack (lane-indexed, shfl-accessed), lockstep.
    //      FULL UNROLL: literal-lane shfl feeds are hoistable off the serial chain.
    {
        const int base = wrp << 5;
        bA[base + lane] = make_float2(0.0f, 0.0f);      // clear chunk slots
        __syncwarp();

        float psum = 0.0f, pcnt = 0.0f;                 // stack entry owned by this lane
        int   ppos = 0;
        int nb = 0;
        float ts = __shfl_sync(FULL, sval, 0), tc = 1.0f;
        int tpos = 0;
        #pragma unroll
        for (int i = 1; i < 32; i++) {
            float cs = __shfl_sync(FULL, sval, i), cc = 1.0f;
            int cpos = i;
            for (;;) {
                if (cs * tc > ts * cc) {                // cur_mean > top_mean: pool
                    cs += ts; cc += tc; cpos = tpos;
                    if (nb > 0) {
                        --nb;
                        ts   = __shfl_sync(FULL, psum, nb);
                        tc   = __shfl_sync(FULL, pcnt, nb);
                        tpos = __shfl_sync(FULL, ppos, nb);
                    } else { ts = cs; tc = cc; tpos = cpos; goto nexti; }
                } else break;
            }
            if (lane == nb) { psum = ts; pcnt = tc; ppos = tpos; }
            nb++;
            ts = cs; tc = cc; tpos = cpos;
            nexti: ;
        }
        if (lane == nb) { psum = ts; pcnt = tc; ppos = tpos; }
        nb++;

        if (lane < nb) {
            int st = base + ppos;
            int c  = (int)pcnt;
            bA[st] = make_float2(psum, pcnt);
            if (c > 1) {
                jr[st + 1]     = st + c;
                jl[st + c - 1] = st;
            }
        }
    }
    __syncthreads();     // bA, jl/jr visible

    // ---- merge tree: 5 levels, one cascade per WARP ----
    #pragma unroll 1
    for (int L = 0; L < 5; L++) {
        int npairs = 16 >> L;
        if (lane == 0 && wrp < npairs) {
            int seg = 64 << L;
            int ls  = wrp * seg;
            cascade(bA, jl, jr, ls, ls + (seg >> 1), ls + seg);
        }
        __syncthreads();
    }

    // ---- fill-forward: valid slot index max-scan gives each position its block start ----
    float2 bme = bA[tid];
    int mp = (bme.y > 0.0f) ? tid : -1;
    #pragma unroll
    for (int o = 1; o < 32; o <<= 1) {
        int t = __shfl_up_sync(FULL, mp, o);
        if (lane >= o) mp = max(mp, t);
    }
    if (lane == 31) part_b[wrp] = mp;
    __syncthreads();
    if (tid < 32) {
        int p = part_b[tid];
        #pragma unroll
        for (int o = 1; o < 32; o <<= 1) {
            int t = __shfl_up_sync(FULL, p, o);
            if (tid >= o) p = max(p, t);
        }
        part_b[tid] = p;
    }
    __syncthreads();
    if (wrp > 0) mp = max(mp, part_b[wrp - 1]);

    float2 blk = bA[mp];                       // block containing position tid
    float y = fmaxf(blk.x / blk.y, 0.0f);      // pooled mean, clamped; nonincreasing in tid
    float z = sgn_i * y;                       // oscar prox at sorted position tid

    // ---- fused epilogue: one combined scan -> rank AND sorted cumsum ----
    {
        int fP = (z > 0.0f) ? 1 : 0;
        int fN = (z < 0.0f) ? 1 : 0;
        int   pk = (fP << 16) | fN;
        float zp = fP ? z : 0.0f;
        float zn = fN ? z : 0.0f;
        int   ipk = pk;
        float izp = zp, izn = zn;
        #pragma unroll
        for (int o = 1; o < 32; o <<= 1) {
            int   ti = __shfl_up_sync(FULL, ipk, o);
            float tp = __shfl_up_sync(FULL, izp, o);
            float tn = __shfl_up_sync(FULL, izn, o);
            if (lane >= o) { ipk += ti; izp += tp; izn += tn; }
        }
        if (lane == 31) { part_c[wrp] = ipk; part_p[wrp] = izp; part_n[wrp] = izn; }
        __syncthreads();
        if (tid < 32) {
            int   p  = part_c[tid];
            float pp = part_p[tid];
            float pn = part_n[tid];
            #pragma unroll
            for (int o = 1; o < 32; o <<= 1) {
                int   ti = __shfl_up_sync(FULL, p,  o);
                float tp = __shfl_up_sync(FULL, pp, o);
                float tn = __shfl_up_sync(FULL, pn, o);
                if (tid >= o) { p += ti; pp += tp; pn += tn; }
            }
            part_c[tid] = p; part_p[tid] = pp; part_n[tid] = pn;
        }
        __syncthreads();
        if (wrp > 0) {
            ipk += part_c[wrp - 1];
            izp += part_p[wrp - 1];
            izn += part_n[wrp - 1];
        }
        int   total = part_c[31];
        float totP  = part_p[31];
        float totN  = part_n[31];

        int excl = ipk - pk;
        int pPex = excl >> 16;
        int pNex = excl & 0xffff;
        int totalPcnt = total >> 16;

        int pos;
        float c;
        if (z > 0.0f)      { pos = pPex;                            c = izp; }
        else if (z < 0.0f) { pos = DD - 1 - pNex;                   c = (totP + totN) - (izn - zn); }
        else               { pos = totalPcnt + (tid - pPex - pNex); c = totP; }

        bool flag = (1.0f + (float)(pos + 1) * z) > c;
        int k_sup = __syncthreads_count(flag);        // support is a prefix in sorted order
        if (pos == k_sup - 1) tau_sh = (c - 1.0f) / (float)k_sup;
        __syncthreads();

        out[row * DD + idx] = fmaxf(z - tau_sh, 0.0f);
    }
}

extern "C" void kernel_launch(void* const* d_in, const int* in_sizes, int n_in,
                              void* d_out, int out_size) {
    const float* x = (const float*)d_in[0];
    float* out = (float*)d_out;
    oscarmax_kernel<<<BB, DD>>>(x, out);
}

// round 15
// speedup vs baseline: 1.0158x; 1.0039x over previous
#include <cuda_runtime.h>

typedef unsigned long long u64;
typedef unsigned int u32;

#define DD 1024
#define BB 64
#define BETA_W 0.001f

// Junction cascade over a gapped, position-indexed block array with edge pointers.
__device__ void cascade(float2* b, int* jl, int* jr, int ls, int junc, int re) {
    int li = junc - 1;
    float2 L = b[li];
    if (L.y == 0.0f) { li = jl[li]; L = b[li]; }
    float2 P = b[junc];
    if (!(L.x * P.y < P.x * L.y)) return;
    P.x += L.x; P.y += L.y;
    b[li].y = 0.0f;
    b[junc].y = 0.0f;
    int lpos = li;
    int lc = li - 1;
    int rc = junc + 1;
    int lstop = ls - 1;
    int rstop = re;
    bool changed = true;
    while (changed) {
        changed = false;
        while (lc >= ls) {
            float2 Lb = b[lc];
            if (Lb.y == 0.0f) { lc = jl[lc]; if (lc < ls) break; Lb = b[lc]; }
            if (Lb.x * P.y < P.x * Lb.y) {
                P.x += Lb.x; P.y += Lb.y;
                b[lc].y = 0.0f;
                lpos = lc; --lc; changed = true;
            } else { lstop = lc; break; }
        }
        while (rc < re) {
            float2 Rb = b[rc];
            if (Rb.y == 0.0f) { rc = jr[rc]; if (rc >= re) break; Rb = b[rc]; }
            if (Rb.x * P.y > P.x * Rb.y) {
                P.x += Rb.x; P.y += Rb.y;
                b[rc].y = 0.0f;
                ++rc; changed = true;
            } else { rstop = rc; break; }
        }
    }
    b[lpos] = P;
    if (lpos - 1 > lstop) { jl[lpos - 1] = lstop; jr[lstop + 1] = lpos; }
    if (rstop - 1 > lpos) { jl[rstop - 1] = lpos; jr[lpos + 1] = rstop; }
}

// One weighted PAVA item through the register stack (warp-uniform, lockstep).
// Stack entry b lives in lane b as (psum, pmeta=cnt*32+pos).
__device__ __forceinline__ void pava_item(
    float cs, float cc, int cpos,
    float& ts, float& tc, int& tpos,
    float& psum, float& pmeta, int& nb, int lane, unsigned FULL)
{
    for (;;) {
        if (cs * tc > ts * cc) {                 // cur_mean > top_mean: pool
            cs += ts; cc += tc; cpos = tpos;
            if (nb > 0) {
                --nb;
                float ms = __shfl_sync(FULL, psum, nb);
                int   mi = (int)__shfl_sync(FULL, pmeta, nb);
                ts = ms; tc = (float)(mi >> 5); tpos = mi & 31;
            } else { ts = cs; tc = cc; tpos = cpos; return; }
        } else break;
    }
    if (lane == nb) { psum = ts; pmeta = tc * 32.0f + (float)tpos; }
    nb++;
    ts = cs; tc = cc; tpos = cpos;
}

__global__ __launch_bounds__(1024) void oscarmax_kernel(const float* __restrict__ x,
                                                        float* __restrict__ out) {
    __shared__ u64   sbuf[2][DD];      // scatter buf / sorted buf; after: bA | jl/jr
    __shared__ int   cnt[DD];          // bucket sizes
    __shared__ int   offs[DD];         // scatter offsets (post-scatter: start+size)
    __shared__ int   part_b[32];       // fill max-scan
    __shared__ int   part_c[32];       // bucket scan + rank scan (barrier-separated)
    __shared__ float part_p[32];       // positive-sum scan
    __shared__ float part_n[32];       // negative-sum scan
    __shared__ float tau_sh;

    float2* bA = (float2*)&sbuf[0][0];
    int*    jl = (int*)&sbuf[1][0];
    int*    jr = jl + DD;
    u64*    s64a = &sbuf[0][0];        // scattered (unordered within bucket)
    u64*    s64b = &sbuf[1][0];        // fully sorted

    const int tid  = threadIdx.x;
    const int lane = tid & 31;
    const int wrp  = tid >> 5;
    const int row  = blockIdx.x;
    const unsigned FULL = 0xffffffffu;

    // ---- load, pack sortable u64: key=|x| bits (desc), payload=(idx<<1)|negbit ----
    float xv = x[row * DD + tid];
    float ax = fabsf(xv);
    u32 kb = __float_as_uint(ax);
    u32 pl = ((u32)tid << 1) | (xv < 0.0f ? 1u : 0u);
    u64 v = ((u64)kb << 32) | pl;

    // ---- bucket sort (descending): monotone bucket, exact in-bucket ranking ----
    int bkt = 1023 - min(1023, (int)(ax * 256.0f));   // descending bucket order
    cnt[tid] = 0;
    __syncthreads();
    atomicAdd(&cnt[bkt], 1);
    __syncthreads();

    // exclusive scan of cnt -> offs (scatter cursor)
    {
        int csz = cnt[tid];
        int inc = csz;
        #pragma unroll
        for (int o = 1; o < 32; o <<= 1) {
            int t = __shfl_up_sync(FULL, inc, o);
            if (lane >= o) inc += t;
        }
        if (lane == 31) part_c[wrp] = inc;
        __syncthreads();
        if (tid < 32) {
            int p = part_c[tid];
            #pragma unroll
            for (int o = 1; o < 32; o <<= 1) {
                int t = __shfl_up_sync(FULL, p, o);
                if (tid >= o) p += t;
            }
            part_c[tid] = p;
        }
        __syncthreads();
        if (wrp > 0) inc += part_c[wrp - 1];
        offs[tid] = inc - csz;
    }
    __syncthreads();

    // scatter into bucket region (unordered within bucket)
    {
        int slot = atomicAdd(&offs[bkt], 1);
        s64a[slot] = v;
    }
    __syncthreads();

    // exact within-bucket rank (descending): r = #{peer > v}; place at start+r
    {
        int sz = cnt[bkt];
        int st = offs[bkt] - sz;        // post-scatter offs[bkt] == start + size
        int r = 0;
        #pragma unroll 1
        for (int q = 0; q < sz; q++) {
            u64 u = s64a[st + q];
            r += (u > v) ? 1 : 0;
        }
        s64b[st + r] = v;
    }
    __syncthreads();
    v = s64b[tid];      // fully sorted descending, strict total order -> deterministic

    // ---- unpack: key, index, sign all from the sorted word ----
    float keyf  = __uint_as_float((u32)(v >> 32));
    u32   plo   = (u32)v;
    int   idx   = (int)(plo >> 1);
    float sgn_i = (plo & 1u) ? -1.0f : 1.0f;
    float sval  = keyf - BETA_W * (float)(DD - 1 - tid);
    __syncthreads();     // all sorted reads done; sbuf dead -> bA / jl / jr

    // ---- per-chunk PAVA with parallel pair pre-pass + register stack ----
    {
        const int base = wrp << 5;
        bA[base + lane] = make_float2(0.0f, 0.0f);      // clear chunk slots
        __syncwarp();

        // pre-pass: slot = lane (valid for lane<16): pair (2*slot, 2*slot+1)
        float s0 = __shfl_sync(FULL, sval, (lane * 2) & 31);
        float s1 = __shfl_sync(FULL, sval, (lane * 2 + 1) & 31);
        int   pooled = (s1 > s0) ? 1 : 0;               // legal adjacent-violator pool

        float psum = 0.0f, pmeta = 0.0f;                // stack entry owned by this lane
        int nb = 0;
        float ts, tc; int tpos;

        // slot 0 initializes the top
        {
            float c0 = __shfl_sync(FULL, s0, 0);
            float c1 = __shfl_sync(FULL, s1, 0);
            int   pq = __shfl_sync(FULL, pooled, 0);
            if (pq) { ts = c0 + c1; tc = 2.0f; tpos = 0; }
            else {
                ts = c0; tc = 1.0f; tpos = 0;
                pava_item(c1, 1.0f, 1, ts, tc, tpos, psum, pmeta, nb, lane, FULL);
            }
        }
        #pragma unroll
        for (int i = 1; i < 16; i++) {
            float c0 = __shfl_sync(FULL, s0, i);
            float c1 = __shfl_sync(FULL, s1, i);
            int   pq = __shfl_sync(FULL, pooled, i);
            if (pq) {
                pava_item(c0 + c1, 2.0f, 2 * i, ts, tc, tpos, psum, pmeta, nb, lane, FULL);
            } else {
                pava_item(c0, 1.0f, 2 * i,     ts, tc, tpos, psum, pmeta, nb, lane, FULL);
                pava_item(c1, 1.0f, 2 * i + 1, ts, tc, tpos, psum, pmeta, nb, lane, FULL);
            }
        }
        // final push of top
        if (lane == nb) { psum = ts; pmeta = tc * 32.0f + (float)tpos; }
        nb++;

        // parallel emit: block at slot base+pos; gap edges for cnt>1
        if (lane < nb) {
            int mi = (int)pmeta;
            int st = base + (mi & 31);
            int c  = mi >> 5;
            bA[st] = make_float2(psum, (float)c);
            if (c > 1) {
                jr[st + 1]     = st + c;
                jl[st + c - 1] = st;
            }
        }
    }
    __syncthreads();     // bA, jl/jr visible

    // ---- merge tree: 5 levels, one cascade per WARP ----
    #pragma unroll 1
    for (int L = 0; L < 5; L++) {
        int npairs = 16 >> L;
        if (lane == 0 && wrp < npairs) {
            int seg = 64 << L;
            int ls  = wrp * seg;
            cascade(bA, jl, jr, ls, ls + (seg >> 1), ls + seg);
        }
        __syncthreads();
    }

    // ---- fill-forward: valid slot index max-scan gives each position its block start ----
    float2 bme = bA[tid];
    int mp = (bme.y > 0.0f) ? tid : -1;
    #pragma unroll
    for (int o = 1; o < 32; o <<= 1) {
        int t = __shfl_up_sync(FULL, mp, o);
        if (lane >= o) mp = max(mp, t);
    }
    if (lane == 31) part_b[wrp] = mp;
    __syncthreads();
    if (tid < 32) {
        int p = part_b[tid];
        #pragma unroll
        for (int o = 1; o < 32; o <<= 1) {
            int t = __shfl_up_sync(FULL, p, o);
            if (tid >= o) p = max(p, t);
        }
        part_b[tid] = p;
    }
    __syncthreads();
    if (wrp > 0) mp = max(mp, part_b[wrp - 1]);

    float2 blk = bA[mp];                       // block containing position tid
    float y = fmaxf(blk.x / blk.y, 0.0f);      // pooled mean, clamped; nonincreasing in tid
    float z = sgn_i * y;                       // oscar prox at sorted position tid

    // ---- fused epilogue: one combined scan -> rank AND sorted cumsum ----
    {
        int fP = (z > 0.0f) ? 1 : 0;
        int fN = (z < 0.0f) ? 1 : 0;
        int   pk = (fP << 16) | fN;
        float zp = fP ? z : 0.0f;
        float zn = fN ? z : 0.0f;
        int   ipk = pk;
        float izp = zp, izn = zn;
        #pragma unroll
        for (int o = 1; o < 32; o <<= 1) {
            int   ti = __shfl_up_sync(FULL, ipk, o);
            float tp = __shfl_up_sync(FULL, izp, o);
            float tn = __shfl_up_sync(FULL, izn, o);
            if (lane >= o) { ipk += ti; izp += tp; izn += tn; }
        }
        if (lane == 31) { part_c[wrp] = ipk; part_p[wrp] = izp; part_n[wrp] = izn; }
        __syncthreads();
        if (tid < 32) {
            int   p  = part_c[tid];
            float pp = part_p[tid];
            float pn = part_n[tid];
            #pragma unroll
            for (int o = 1; o < 32; o <<= 1) {
                int   ti = __shfl_up_sync(FULL, p,  o);
                float tp = __shfl_up_sync(FULL, pp, o);
                float tn = __shfl_up_sync(FULL, pn, o);
                if (tid >= o) { p += ti; pp += tp; pn += tn; }
            }
            part_c[tid] = p; part_p[tid] = pp; part_n[tid] = pn;
        }
        __syncthreads();
        if (wrp > 0) {
            ipk += part_c[wrp - 1];
            izp += part_p[wrp - 1];
            izn += part_n[wrp - 1];
        }
        int   total = part_c[31];
        float totP  = part_p[31];
        float totN  = part_n[31];

        int excl = ipk - pk;
        int pPex = excl >> 16;
        int pNex = excl & 0xffff;
        int totalPcnt = total >> 16;

        int pos;
        float c;
        if (z > 0.0f)      { pos = pPex;                            c = izp; }
        else if (z < 0.0f) { pos = DD - 1 - pNex;                   c = (totP + totN) - (izn - zn); }
        else               { pos = totalPcnt + (tid - pPex - pNex); c = totP; }

        bool flag = (1.0f + (float)(pos + 1) * z) > c;
        int k_sup = __syncthreads_count(flag);        // support is a prefix in sorted order
        if (pos == k_sup - 1) tau_sh = (c - 1.0f) / (float)k_sup;
        __syncthreads();

        out[row * DD + idx] = fmaxf(z - tau_sh, 0.0f);
    }
}

extern "C" void kernel_launch(void* const* d_in, const int* in_sizes, int n_in,
                              void* d_out, int out_size) {
    const float* x = (const float*)d_in[0];
    float* out = (float*)d_out;
    oscarmax_kernel<<<BB, DD>>>(x, out);
}

// round 16
// speedup vs baseline: 1.0842x; 1.0674x over previous
#include <cuda_runtime.h>

typedef unsigned long long u64;
typedef unsigned int u32;

#define DD 1024
#define BB 64
#define BETA_W 0.001f

// Junction cascade over a gapped, position-indexed block array with edge pointers.
__device__ void cascade(float2* b, int* jl, int* jr, int ls, int junc, int re) {
    int li = junc - 1;
    float2 L = b[li];
    if (L.y == 0.0f) { li = jl[li]; L = b[li]; }
    float2 P = b[junc];
    if (!(L.x * P.y < P.x * L.y)) return;
    P.x += L.x; P.y += L.y;
    b[li].y = 0.0f;
    b[junc].y = 0.0f;
    int lpos = li;
    int lc = li - 1;
    int rc = junc + 1;
    int lstop = ls - 1;
    int rstop = re;
    bool changed = true;
    while (changed) {
        changed = false;
        while (lc >= ls) {
            float2 Lb = b[lc];
            if (Lb.y == 0.0f) { lc = jl[lc]; if (lc < ls) break; Lb = b[lc]; }
            if (Lb.x * P.y < P.x * Lb.y) {
                P.x += Lb.x; P.y += Lb.y;
                b[lc].y = 0.0f;
                lpos = lc; --lc; changed = true;
            } else { lstop = lc; break; }
        }
        while (rc < re) {
            float2 Rb = b[rc];
            if (Rb.y == 0.0f) { rc = jr[rc]; if (rc >= re) break; Rb = b[rc]; }
            if (Rb.x * P.y > P.x * Rb.y) {
                P.x += Rb.x; P.y += Rb.y;
                b[rc].y = 0.0f;
                ++rc; changed = true;
            } else { rstop = rc; break; }
        }
    }
    b[lpos] = P;
    if (lpos - 1 > lstop) { jl[lpos - 1] = lstop; jr[lstop + 1] = lpos; }
    if (rstop - 1 > lpos) { jl[rstop - 1] = lpos; jr[lpos + 1] = rstop; }
}

// One weighted PAVA item through the register stack (warp-uniform, lockstep).
// Stack entry b lives in lane b as (psum, pmeta=cnt*32+pos).
__device__ __forceinline__ void pava_item(
    float cs, float cc, int cpos,
    float& ts, float& tc, int& tpos,
    float& psum, float& pmeta, int& nb, int lane, unsigned FULL)
{
    for (;;) {
        if (cs * tc > ts * cc) {                 // cur_mean > top_mean: pool
            cs += ts; cc += tc; cpos = tpos;
            if (nb > 0) {
                --nb;
                float ms = __shfl_sync(FULL, psum, nb);
                int   mi = (int)__shfl_sync(FULL, pmeta, nb);
                ts = ms; tc = (float)(mi >> 5); tpos = mi & 31;
            } else { ts = cs; tc = cc; tpos = cpos; return; }
        } else break;
    }
    if (lane == nb) { psum = ts; pmeta = tc * 32.0f + (float)tpos; }
    nb++;
    ts = cs; tc = cc; tpos = cpos;
}

__global__ __launch_bounds__(1024) void oscarmax_kernel(const float* __restrict__ x,
                                                        float* __restrict__ out) {
    __shared__ u64   sbuf[2][DD];      // scatter buf / sorted buf; after: bA | jl/jr
    __shared__ int   cnt[DD];          // bucket sizes
    __shared__ int   offs[DD];         // scatter offsets (post-scatter: start+size)
    __shared__ int   part_b[32];       // fill max-scan (per-warp last valid slot)
    __shared__ int   part_c[32];       // bucket scan + packed P/N counts
    __shared__ float part_p[32];       // positive-sum scan
    __shared__ float part_n[32];       // negative-sum scan
    __shared__ float tau_sh;

    float2* bA = (float2*)&sbuf[0][0];
    int*    jl = (int*)&sbuf[1][0];
    int*    jr = jl + DD;
    u64*    s64a = &sbuf[0][0];        // scattered (unordered within bucket)
    u64*    s64b = &sbuf[1][0];        // fully sorted

    const int tid  = threadIdx.x;
    const int lane = tid & 31;
    const int wrp  = tid >> 5;
    const int row  = blockIdx.x;
    const unsigned FULL = 0xffffffffu;

    // ---- load, pack sortable u64: key=|x| bits (desc), payload=(idx<<1)|negbit ----
    float xv = x[row * DD + tid];
    float ax = fabsf(xv);
    u32 kb = __float_as_uint(ax);
    u32 pl = ((u32)tid << 1) | (xv < 0.0f ? 1u : 0u);
    u64 v = ((u64)kb << 32) | pl;

    // ---- bucket sort (descending): monotone bucket, exact in-bucket ranking ----
    int bkt = 1023 - min(1023, (int)(ax * 256.0f));   // descending bucket order
    cnt[tid] = 0;
    __syncthreads();
    atomicAdd(&cnt[bkt], 1);
    __syncthreads();

    // exclusive scan of cnt -> offs (scatter cursor)
    {
        int csz = cnt[tid];
        int inc = csz;
        #pragma unroll
        for (int o = 1; o < 32; o <<= 1) {
            int t = __shfl_up_sync(FULL, inc, o);
            if (lane >= o) inc += t;
        }
        if (lane == 31) part_c[wrp] = inc;
        __syncthreads();
        if (tid < 32) {
            int p = part_c[tid];
            #pragma unroll
            for (int o = 1; o < 32; o <<= 1) {
                int t = __shfl_up_sync(FULL, p, o);
                if (tid >= o) p += t;
            }
            part_c[tid] = p;
        }
        __syncthreads();
        if (wrp > 0) inc += part_c[wrp - 1];
        offs[tid] = inc - csz;
    }
    __syncthreads();

    // scatter into bucket region (unordered within bucket)
    {
        int slot = atomicAdd(&offs[bkt], 1);
        s64a[slot] = v;
    }
    __syncthreads();

    // exact within-bucket rank (descending): r = #{peer > v}; place at start+r
    {
        int sz = cnt[bkt];
        int st = offs[bkt] - sz;        // post-scatter offs[bkt] == start + size
        int r = 0;
        #pragma unroll 1
        for (int q = 0; q < sz; q++) {
            u64 u = s64a[st + q];
            r += (u > v) ? 1 : 0;
        }
        s64b[st + r] = v;
    }
    __syncthreads();
    v = s64b[tid];      // fully sorted descending, strict total order -> deterministic

    // ---- unpack: key, index, sign all from the sorted word ----
    float keyf  = __uint_as_float((u32)(v >> 32));
    u32   plo   = (u32)v;
    int   idx   = (int)(plo >> 1);
    float sgn_i = (plo & 1u) ? -1.0f : 1.0f;
    float sval  = keyf - BETA_W * (float)(DD - 1 - tid);
    __syncthreads();     // all sorted reads done; sbuf dead -> bA / jl / jr

    // ---- per-chunk PAVA with parallel pair pre-pass + register stack ----
    {
        const int base = wrp << 5;
        bA[base + lane] = make_float2(0.0f, 0.0f);      // clear chunk slots
        __syncwarp();

        float s0 = __shfl_sync(FULL, sval, (lane * 2) & 31);
        float s1 = __shfl_sync(FULL, sval, (lane * 2 + 1) & 31);

        float psum = 0.0f, pmeta = 0.0f;                // stack entry owned by this lane
        int nb = 0;
        float ts, tc; int tpos;

        // slot 0 initializes the top
        {
            float c0 = __shfl_sync(FULL, s0, 0);
            float c1 = __shfl_sync(FULL, s1, 0);
            if (c1 > c0) { ts = c0 + c1; tc = 2.0f; tpos = 0; }
            else {
                ts = c0; tc = 1.0f; tpos = 0;
                pava_item(c1, 1.0f, 1, ts, tc, tpos, psum, pmeta, nb, lane, FULL);
            }
        }
        #pragma unroll
        for (int i = 1; i < 16; i++) {
            float c0 = __shfl_sync(FULL, s0, i);
            float c1 = __shfl_sync(FULL, s1, i);
            if (c1 > c0) {
                pava_item(c0 + c1, 2.0f, 2 * i, ts, tc, tpos, psum, pmeta, nb, lane, FULL);
            } else {
                pava_item(c0, 1.0f, 2 * i,     ts, tc, tpos, psum, pmeta, nb, lane, FULL);
                pava_item(c1, 1.0f, 2 * i + 1, ts, tc, tpos, psum, pmeta, nb, lane, FULL);
            }
        }
        if (lane == nb) { psum = ts; pmeta = tc * 32.0f + (float)tpos; }
        nb++;

        // parallel emit: block at slot base+pos; gap edges for cnt>1
        if (lane < nb) {
            int mi = (int)pmeta;
            int st = base + (mi & 31);
            int c  = mi >> 5;
            bA[st] = make_float2(psum, (float)c);
            if (c > 1) {
                jr[st + 1]     = st + c;
                jl[st + c - 1] = st;
            }
        }
    }
    __syncthreads();     // bA, jl/jr visible

    // ---- merge tree: 5 levels, one cascade per WARP ----
    #pragma unroll 1
    for (int L = 0; L < 5; L++) {
        int npairs = 16 >> L;
        if (lane == 0 && wrp < npairs) {
            int seg = 64 << L;
            int ls  = wrp * seg;
            cascade(bA, jl, jr, ls, ls + (seg >> 1), ls + seg);
        }
        __syncthreads();
    }

    // ---- fill-forward via ballot: last valid slot <= tid ----
    float2 bme = bA[tid];
    int mp;
    {
        unsigned vm = __ballot_sync(FULL, bme.y > 0.0f);
        unsigned lemask = (2u << lane) - 1u;             // lanes <= lane (lane=31 -> all)
        int mw = 31 - __clz((int)(vm & lemask));         // clz(0)=32 -> -1
        int mp_in = (mw >= 0) ? (tid & ~31) + mw : -1;
        if (lane == 0) {
            int lw = (vm != 0u) ? (tid & ~31) + (31 - __clz((int)vm)) : -1;
            part_b[wrp] = lw;
        }
        __syncthreads();
        if (tid < 32) {
            int p = part_b[tid];
            #pragma unroll
            for (int o = 1; o < 32; o <<= 1) {
                int t = __shfl_up_sync(FULL, p, o);
                if (tid >= o) p = max(p, t);
            }
            part_b[tid] = p;
        }
        __syncthreads();
        mp = max(mp_in, (wrp > 0) ? part_b[wrp - 1] : -1);
    }

    float2 blk = bA[mp];                       // block containing position tid
    float y = fmaxf(blk.x / blk.y, 0.0f);      // pooled mean, clamped; nonincreasing in tid
    float z = sgn_i * y;                       // oscar prox at sorted position tid

    // ---- fused epilogue: ballot ranks + 2-wide float scan -> sorted cumsum ----
    {
        bool isP = (z > 0.0f);
        bool isN = (z < 0.0f);
        unsigned mPm = __ballot_sync(FULL, isP);
        unsigned mNm = __ballot_sync(FULL, isN);
        unsigned ltm = (1u << lane) - 1u;
        int pPw = __popc(mPm & ltm);           // exclusive P-count within warp
        int pNw = __popc(mNm & ltm);

        float zp = isP ? z : 0.0f;
        float zn = isN ? z : 0.0f;
        float izp = zp, izn = zn;
        #pragma unroll
        for (int o = 1; o < 32; o <<= 1) {
            float tp = __shfl_up_sync(FULL, izp, o);
            float tn = __shfl_up_sync(FULL, izn, o);
            if (lane >= o) { izp += tp; izn += tn; }
        }
        if (lane == 31) {
            part_c[wrp] = (__popc(mPm) << 16) | __popc(mNm);
            part_p[wrp] = izp;
            part_n[wrp] = izn;
        }
        __syncthreads();
        if (tid < 32) {
            int   p  = part_c[tid];
            float pp = part_p[tid];
            float pn = part_n[tid];
            #pragma unroll
            for (int o = 1; o < 32; o <<= 1) {
                int   ti = __shfl_up_sync(FULL, p,  o);
                float tp = __shfl_up_sync(FULL, pp, o);
                float tn = __shfl_up_sync(FULL, pn, o);
                if (tid >= o) { p += ti; pp += tp; pn += tn; }
            }
            part_c[tid] = p; part_p[tid] = pp; part_n[tid] = pn;
        }
        __syncthreads();
        int cEx = (wrp > 0) ? part_c[wrp - 1] : 0;
        if (wrp > 0) { izp += part_p[wrp - 1]; izn += part_n[wrp - 1]; }

        int pPex = (cEx >> 16) + pPw;
        int pNex = (cEx & 0xffff) + pNw;
        int totalPcnt = part_c[31] >> 16;
        float totP = part_p[31];
        float totN = part_n[31];

        int pos;
        float c;
        if (isP)      { pos = pPex;                            c = izp; }
        else if (isN) { pos = DD - 1 - pNex;                   c = (totP + totN) - (izn - zn); }
        else          { pos = totalPcnt + (tid - pPex - pNex); c = totP; }

        bool flag = (1.0f + (float)(pos + 1) * z) > c;
        int k_sup = __syncthreads_count(flag);        // support is a prefix in sorted order
        if (pos == k_sup - 1) tau_sh = (c - 1.0f) / (float)k_sup;
        __syncthreads();

        out[row * DD + idx] = fmaxf(z - tau_sh, 0.0f);
    }
}

extern "C" void kernel_launch(void* const* d_in, const int* in_sizes, int n_in,
                              void* d_out, int out_size) {
    const float* x = (const float*)d_in[0];
    float* out = (float*)d_out;
    oscarmax_kernel<<<BB, DD>>>(x, out);
}